// round 1
// baseline (speedup 1.0000x reference)
#include <cuda_runtime.h>

// V2STransformer: volume-to-slice affine resample with trilinear interpolation.
// vol: [B, H, W, D, 1] float32   (B=8, H=160, W=160, D=96)
// trf: [B, S, 12]       float32  (S=64, per-slice 3x4 affine, identity added here)
// out: [B, H, W, S, 1]  float32
//
// Thread mapping: threadIdx.x = s (64, coalesced output writes + D-contiguous
// gathers since loc.z ~ 1.5*s), threadIdx.y = w-subtile (4), grid = (W/4, H, B).

#define BB 8
#define HH 160
#define WW 160
#define DD 96
#define SS 64
#define ST_RATIO 1.5f

__global__ __launch_bounds__(256, 4)
void v2s_kernel(const float* __restrict__ vol,
                const float* __restrict__ trf,
                float* __restrict__ out) {
    // Per-(b,s) affine matrices, identity pre-added. Stride 13 (coprime with
    // 32 banks) so lane-varying s reads are conflict-free.
    __shared__ float As[SS][13];

    const int s  = threadIdx.x;                 // 0..63
    const int w  = blockIdx.x * 4 + threadIdx.y; // 0..159
    const int h  = blockIdx.y;                  // 0..159
    const int b  = blockIdx.z;                  // 0..7

    // Cooperative load of this batch's 64 affines (768 floats) into shared.
    const int tid = threadIdx.y * 64 + threadIdx.x;
    #pragma unroll
    for (int k = tid; k < SS * 12; k += 256) {
        const int ss = k / 12;
        const int e  = k % 12;
        float v = trf[((size_t)b * SS + ss) * 12 + e];
        // A = trf.reshape(3,4) + eye(4)[:3,:]  -> +1 at flat indices 0, 5, 10
        if (e == 0 || e == 5 || e == 10) v += 1.0f;
        As[ss][e] = v;
    }
    __syncthreads();

    const float fi = (float)h;
    const float fj = (float)w;
    const float fz = (float)s * ST_RATIO;

    const float* A = As[s];
    float x = fmaf(A[0], fi, fmaf(A[1], fj, fmaf(A[2],  fz, A[3])));
    float y = fmaf(A[4], fi, fmaf(A[5], fj, fmaf(A[6],  fz, A[7])));
    float z = fmaf(A[8], fi, fmaf(A[9], fj, fmaf(A[10], fz, A[11])));

    // Border clip (matches reference: clip then floor, i1 = min(i0+1, max))
    x = fminf(fmaxf(x, 0.0f), (float)(HH - 1));
    y = fminf(fmaxf(y, 0.0f), (float)(WW - 1));
    z = fminf(fmaxf(z, 0.0f), (float)(DD - 1));

    const float xf = floorf(x), yf = floorf(y), zf = floorf(z);
    const float dx = x - xf, dy = y - yf, dz = z - zf;
    const int x0 = (int)xf, y0 = (int)yf, z0 = (int)zf;
    const int x1 = min(x0 + 1, HH - 1);
    const int y1 = min(y0 + 1, WW - 1);
    const int z1 = min(z0 + 1, DD - 1);

    const float* __restrict__ vb = vol + (size_t)b * (HH * WW * DD);
    const int r00 = (x0 * WW + y0) * DD;
    const int r01 = (x0 * WW + y1) * DD;
    const int r10 = (x1 * WW + y0) * DD;
    const int r11 = (x1 * WW + y1) * DD;

    const float v000 = __ldg(vb + r00 + z0);
    const float v001 = __ldg(vb + r00 + z1);
    const float v010 = __ldg(vb + r01 + z0);
    const float v011 = __ldg(vb + r01 + z1);
    const float v100 = __ldg(vb + r10 + z0);
    const float v101 = __ldg(vb + r10 + z1);
    const float v110 = __ldg(vb + r11 + z0);
    const float v111 = __ldg(vb + r11 + z1);

    // Trilinear blend via lerps (mathematically identical to the 8-weight sum)
    const float c00 = fmaf(dz, v001 - v000, v000);
    const float c01 = fmaf(dz, v011 - v010, v010);
    const float c10 = fmaf(dz, v101 - v100, v100);
    const float c11 = fmaf(dz, v111 - v110, v110);
    const float c0  = fmaf(dy, c01 - c00, c00);
    const float c1  = fmaf(dy, c11 - c10, c10);
    const float r   = fmaf(dx, c1 - c0, c0);

    // out[b][h][w][s]
    out[(((size_t)b * HH + h) * WW + w) * SS + s] = r;
}

extern "C" void kernel_launch(void* const* d_in, const int* in_sizes, int n_in,
                              void* d_out, int out_size) {
    const float* vol = (const float*)d_in[0];
    const float* trf = (const float*)d_in[1];
    float* out = (float*)d_out;

    dim3 block(64, 4, 1);          // s x w-subtile
    dim3 grid(WW / 4, HH, BB);     // (40, 160, 8)
    v2s_kernel<<<grid, block>>>(vol, trf, out);
}

// round 2
// speedup vs baseline: 2.2692x; 2.2692x over previous
#include <cuda_runtime.h>

// V2STransformer: volume-to-slice affine resample with trilinear interpolation.
// vol: [B, H, W, D] f32 (B=8,H=160,W=160,D=96), trf: [B,S,12] (S=64), out: [B,H,W,S].
//
// Two-pass design:
//  1) transpose vol -> vol_t [B, H, D, W]  (W contiguous)
//  2) main kernel: lanes = w so each warp shares one affine and gathers are
//     ~consecutive in W -> 2-3 L1 lines per LDG instead of ~30. Output staged
//     in shared and written coalesced along S.

#define BB 8
#define HH 160
#define WW 160
#define DD 96
#define SS 64
#define ST_RATIO 1.5f

// Scratch: transposed volume [b][h][d][w]  (8*160*96*160 floats = 78.6 MB)
__device__ float vol_t_buf[(size_t)BB * HH * DD * WW];

// ---------------------------------------------------------------------------
// Pass 1: per-(b,h) 2D transpose of [W, D] -> [D, W]. 160 = 5*32, 96 = 3*32.
// ---------------------------------------------------------------------------
__global__ __launch_bounds__(256)
void v2s_transpose_kernel(const float* __restrict__ vol) {
    __shared__ float tile[32][33];

    const int bh = blockIdx.z;              // b*H + h
    const int d0 = blockIdx.x * 32;
    const int w0 = blockIdx.y * 32;
    const int tx = threadIdx.x;             // 32
    const int ty = threadIdx.y;             // 8

    const float* __restrict__ src = vol + (size_t)bh * WW * DD;   // [w][d]
    float* __restrict__ dst = vol_t_buf + (size_t)bh * DD * WW;   // [d][w]

    #pragma unroll
    for (int i = 0; i < 32; i += 8) {
        // read coalesced along d
        tile[ty + i][tx] = src[(size_t)(w0 + ty + i) * DD + (d0 + tx)];
    }
    __syncthreads();
    #pragma unroll
    for (int i = 0; i < 32; i += 8) {
        // write coalesced along w
        dst[(size_t)(d0 + ty + i) * WW + (w0 + tx)] = tile[tx][ty + i];
    }
}

// ---------------------------------------------------------------------------
// Pass 2: main resample. Block = (32 w-lanes, 8), covers (1 h, 32 w, 64 s).
// Each thread computes 8 s values; warp lanes share the affine per s.
// ---------------------------------------------------------------------------
__global__ __launch_bounds__(256, 4)
void v2s_main_kernel(const float* __restrict__ trf,
                     float* __restrict__ out) {
    __shared__ float As[SS][13];             // identity pre-added, pad 13
    __shared__ float tile[32][SS + 1];       // [w_local][s]

    const int b  = blockIdx.z;
    const int h  = blockIdx.y;
    const int w0 = blockIdx.x * 32;
    const int tx = threadIdx.x;              // w lane: 0..31
    const int ty = threadIdx.y;              // 0..7
    const int tid = ty * 32 + tx;

    // Load this batch's 64 affines (768 floats), add identity.
    #pragma unroll
    for (int k = tid; k < SS * 12; k += 256) {
        const int ss = k / 12;
        const int e  = k % 12;
        float v = trf[((size_t)b * SS + ss) * 12 + e];
        if (e == 0 || e == 5 || e == 10) v += 1.0f;
        As[ss][e] = v;
    }
    __syncthreads();

    const float* __restrict__ vt = vol_t_buf + (size_t)b * (HH * DD * WW);
    const float fi = (float)h;
    const float fj = (float)(w0 + tx);

    #pragma unroll
    for (int k = 0; k < 8; k++) {
        const int s = ty * 8 + k;            // all lanes in warp share s
        const float fz = (float)s * ST_RATIO;
        const float* A = As[s];

        float x = fmaf(A[0], fi, fmaf(A[1], fj, fmaf(A[2],  fz, A[3])));
        float y = fmaf(A[4], fi, fmaf(A[5], fj, fmaf(A[6],  fz, A[7])));
        float z = fmaf(A[8], fi, fmaf(A[9], fj, fmaf(A[10], fz, A[11])));

        x = fminf(fmaxf(x, 0.0f), (float)(HH - 1));
        y = fminf(fmaxf(y, 0.0f), (float)(WW - 1));
        z = fminf(fmaxf(z, 0.0f), (float)(DD - 1));

        const float xf = floorf(x), yf = floorf(y), zf = floorf(z);
        const float dx = x - xf, dy = y - yf, dz = z - zf;
        const int x0 = (int)xf, y0 = (int)yf, z0 = (int)zf;
        const int x1 = min(x0 + 1, HH - 1);
        const int y1 = min(y0 + 1, WW - 1);
        const int z1 = min(z0 + 1, DD - 1);

        // transposed layout: addr = (x*D + z)*W + y  -> lanes ~consecutive in y
        const int r00 = (x0 * DD + z0) * WW;
        const int r01 = (x0 * DD + z1) * WW;
        const int r10 = (x1 * DD + z0) * WW;
        const int r11 = (x1 * DD + z1) * WW;

        const float v000 = __ldg(vt + r00 + y0);
        const float v001 = __ldg(vt + r00 + y1);
        const float v010 = __ldg(vt + r01 + y0);
        const float v011 = __ldg(vt + r01 + y1);
        const float v100 = __ldg(vt + r10 + y0);
        const float v101 = __ldg(vt + r10 + y1);
        const float v110 = __ldg(vt + r11 + y0);
        const float v111 = __ldg(vt + r11 + y1);

        // lerp: y (dy) innermost, then z (dz), then x (dx)
        const float c00 = fmaf(dy, v001 - v000, v000);   // (x0,z0)
        const float c01 = fmaf(dy, v011 - v010, v010);   // (x0,z1)
        const float c10 = fmaf(dy, v101 - v100, v100);   // (x1,z0)
        const float c11 = fmaf(dy, v111 - v110, v110);   // (x1,z1)
        const float c0  = fmaf(dz, c01 - c00, c00);
        const float c1  = fmaf(dz, c11 - c10, c10);
        const float r   = fmaf(dx, c1 - c0, c0);

        tile[tx][s] = r;
    }
    __syncthreads();

    // Coalesced write: consecutive tids -> consecutive s.
    float* __restrict__ ob = out + (((size_t)b * HH + h) * WW + w0) * SS;
    #pragma unroll
    for (int idx = tid; idx < 32 * SS; idx += 256) {
        const int wl = idx >> 6;
        const int s  = idx & 63;
        ob[(size_t)wl * SS + s] = tile[wl][s];
    }
}

extern "C" void kernel_launch(void* const* d_in, const int* in_sizes, int n_in,
                              void* d_out, int out_size) {
    const float* vol = (const float*)d_in[0];
    const float* trf = (const float*)d_in[1];
    float* out = (float*)d_out;

    {
        dim3 block(32, 8, 1);
        dim3 grid(DD / 32, WW / 32, BB * HH);   // (3, 5, 1280)
        v2s_transpose_kernel<<<grid, block>>>(vol);
    }
    {
        dim3 block(32, 8, 1);
        dim3 grid(WW / 32, HH, BB);             // (5, 160, 8)
        v2s_main_kernel<<<grid, block>>>(trf, out);
    }
}